// round 8
// baseline (speedup 1.0000x reference)
#include <cuda_runtime.h>

typedef unsigned long long ull;

#define BATCH   8
#define TLEN    16384
#define CH      32
#define NB      6
#define NT      288
#define NWARPS  9
#define HALO    63
#define SLOTS   1152            /* 4 slots per thread */
#define SROW    1152
#define T_TILE  1026            /* SLOTS - 2*HALO */
#define NTILES  16              /* 16*1026 = 16416 >= 16384 */
#define NCTAS   (BATCH*NTILES)  /* 128 */

#define BUFSZ     7264          /* gate 6144 + skip 1024 + 3x32 biases */
#define OFF_HB    0
#define OFF_BUF0  (CH*SROW)             /* 36864 */
#define OFF_BUF1  (OFF_BUF0 + BUFSZ)
#define OFF_WF    (OFF_BUF1 + BUFSZ)
#define OFF_BFIN  (OFF_WF + 1024)
#define OFF_WI    (OFF_BFIN + 32)
#define OFF_BI    (OFF_WI + 32)
#define OFF_RED   (OFF_BI + 32)
#define OFF_DONE  (OFF_RED + 2*NWARPS)
#define SMEM_FLOATS (OFF_DONE + 1)
#define SMEM_BYTES  (SMEM_FLOATS*4)     /* ~205 KB */

/* in-buffer float offsets */
#define B_WT 0
#define B_WS 3072
#define B_WK 6144
#define B_BT 7168
#define B_BS 7200
#define B_BK 7232

__device__ float g_partials[NCTAS*2];
__device__ unsigned int g_count;

__device__ __forceinline__ void fma2(ull& d, ull a, ull b){
    asm("fma.rn.f32x2 %0, %1, %2, %0;" : "+l"(d) : "l"(a), "l"(b));
}
__device__ __forceinline__ ull pack2(float lo, float hi){
    ull r; asm("mov.b64 %0, {%1, %2};" : "=l"(r) : "f"(lo), "f"(hi)); return r;
}
__device__ __forceinline__ ull packdup(float v){ return pack2(v, v); }
__device__ __forceinline__ void unpack2(ull v, float& lo, float& hi){
    asm("mov.b64 {%0, %1}, %2;" : "=f"(lo), "=f"(hi) : "l"(v));
}
__device__ __forceinline__ float ex2_(float x){
    float y; asm("ex2.approx.f32 %0, %1;" : "=f"(y) : "f"(x)); return y;
}
__device__ __forceinline__ float rcp_(float x){
    float y; asm("rcp.approx.f32 %0, %1;" : "=f"(y) : "f"(x)); return y;
}
/* tanh(a)*sigmoid(g) = (e1-1)*e2 / ((e1+1)(e2+1)), e1=e^{2a}, e2=e^{g}; clamps keep exp finite */
__device__ __forceinline__ float gateval(float a, float g){
    a = fminf(fmaxf(a, -15.f), 15.f);
    g = fminf(fmaxf(g, -30.f), 30.f);
    float e1 = ex2_(a * 2.8853900817779268f);
    float e2 = ex2_(g * 1.4426950408889634f);
    return (e1 - 1.f) * e2 * rcp_((e1 + 1.f) * (e2 + 1.f));
}

__device__ __forceinline__ void copyw(float* dst,
    const float* wt, const float* ws, const float* wk,
    const float* bt, const float* bs, const float* bk, int blk, int tid)
{
    const float4* g1 = (const float4*)(wt + blk*3072);
    const float4* g2 = (const float4*)(ws + blk*3072);
    const float4* g3 = (const float4*)(wk + blk*1024);
    float4* d = (float4*)dst;
    for (int j = tid; j < 768; j += NT) d[j]        = g1[j];
    for (int j = tid; j < 768; j += NT) d[768 + j]  = g2[j];
    for (int j = tid; j < 256; j += NT) d[1536 + j] = g3[j];
    if (tid < 32){
        dst[B_BT + tid] = bt[blk*32 + tid];
        dst[B_BS + tid] = bs[blk*32 + tid];
        dst[B_BK + tid] = bk[blk*32 + tid];
    }
}

/* one tap for one branch: 4 channel-pairs x 4 positions = 16 fma2 */
#define TAP16(ACC0,ACC1,ACC2,ACC3, WA, WB, H0,H1,H2,H3) \
    fma2(ACC0[0],WA.x,H0); fma2(ACC0[1],WA.y,H0); fma2(ACC0[2],WB.x,H0); fma2(ACC0[3],WB.y,H0); \
    fma2(ACC1[0],WA.x,H1); fma2(ACC1[1],WA.y,H1); fma2(ACC1[2],WB.x,H1); fma2(ACC1[3],WB.y,H1); \
    fma2(ACC2[0],WA.x,H2); fma2(ACC2[1],WA.y,H2); fma2(ACC2[2],WB.x,H2); fma2(ACC2[3],WB.y,H2); \
    fma2(ACC3[0],WA.x,H3); fma2(ACC3[1],WA.y,H3); fma2(ACC3[2],WB.x,H3); fma2(ACC3[3],WB.y,H3)

/* gate conv: 8 output channels (group), 4 positions share every weight load */
__device__ __forceinline__ void conv8x4(
    const float* __restrict__ wt, const float* __restrict__ ws,
    const float* __restrict__ bt, const float* __restrict__ bs,
    const float* __restrict__ hb, int tid, int d,
    ull* __restrict__ g0, ull* __restrict__ g1,
    ull* __restrict__ g2, ull* __restrict__ g3)
{
    const int p0 = tid, p1 = tid + NT, p2 = tid + 2*NT, p3 = tid + 3*NT;
    int m0 = p0 - d; if (m0 < 0) m0 = 0;
    const int m1 = p1 - d, m2 = p2 - d, m3 = p3 - d;
    const int q0 = p0 + d, q1 = p1 + d, q2 = p2 + d;
    int q3 = p3 + d; if (q3 > SLOTS-1) q3 = SLOTS-1;

    ull t0_[4], t1_[4], t2_[4], t3_[4];
    ull u0_[4], u1_[4], u2_[4], u3_[4];
    #pragma unroll
    for (int j = 0; j < 4; ++j){
        ull bT = pack2(bt[2*j], bt[2*j+1]);
        ull bS = pack2(bs[2*j], bs[2*j+1]);
        t0_[j]=bT; t1_[j]=bT; t2_[j]=bT; t3_[j]=bT;
        u0_[j]=bS; u1_[j]=bS; u2_[j]=bS; u3_[j]=bS;
    }

    #pragma unroll 1
    for (int ci = 0; ci < CH; ++ci){
        const float* hr  = hb + ci*SROW;
        const float* wtc = wt + ci*CH;
        const float* wsc = ws + ci*CH;
        /* tap 0 : t - d */
        {
            ull h0=packdup(hr[m0]), h1=packdup(hr[m1]), h2=packdup(hr[m2]), h3=packdup(hr[m3]);
            ulonglong2 wa = *(const ulonglong2*)(wtc);
            ulonglong2 wb = *(const ulonglong2*)(wtc + 4);
            ulonglong2 va = *(const ulonglong2*)(wsc);
            ulonglong2 vb = *(const ulonglong2*)(wsc + 4);
            TAP16(t0_,t1_,t2_,t3_, wa, wb, h0,h1,h2,h3);
            TAP16(u0_,u1_,u2_,u3_, va, vb, h0,h1,h2,h3);
        }
        /* tap 1 : t */
        {
            ull h0=packdup(hr[p0]), h1=packdup(hr[p1]), h2=packdup(hr[p2]), h3=packdup(hr[p3]);
            ulonglong2 wa = *(const ulonglong2*)(wtc + 1024);
            ulonglong2 wb = *(const ulonglong2*)(wtc + 1028);
            ulonglong2 va = *(const ulonglong2*)(wsc + 1024);
            ulonglong2 vb = *(const ulonglong2*)(wsc + 1028);
            TAP16(t0_,t1_,t2_,t3_, wa, wb, h0,h1,h2,h3);
            TAP16(u0_,u1_,u2_,u3_, va, vb, h0,h1,h2,h3);
        }
        /* tap 2 : t + d */
        {
            ull h0=packdup(hr[q0]), h1=packdup(hr[q1]), h2=packdup(hr[q2]), h3=packdup(hr[q3]);
            ulonglong2 wa = *(const ulonglong2*)(wtc + 2048);
            ulonglong2 wb = *(const ulonglong2*)(wtc + 2052);
            ulonglong2 va = *(const ulonglong2*)(wsc + 2048);
            ulonglong2 vb = *(const ulonglong2*)(wsc + 2052);
            TAP16(t0_,t1_,t2_,t3_, wa, wb, h0,h1,h2,h3);
            TAP16(u0_,u1_,u2_,u3_, va, vb, h0,h1,h2,h3);
        }
    }
    #pragma unroll
    for (int j = 0; j < 4; ++j){
        float a0,a1,b0,b1;
        unpack2(t0_[j],a0,a1); unpack2(u0_[j],b0,b1);
        g0[j] = pack2(gateval(a0,b0), gateval(a1,b1));
        unpack2(t1_[j],a0,a1); unpack2(u1_[j],b0,b1);
        g1[j] = pack2(gateval(a0,b0), gateval(a1,b1));
        unpack2(t2_[j],a0,a1); unpack2(u2_[j],b0,b1);
        g2[j] = pack2(gateval(a0,b0), gateval(a1,b1));
        unpack2(t3_[j],a0,a1); unpack2(u3_[j],b0,b1);
        g3[j] = pack2(gateval(a0,b0), gateval(a1,b1));
    }
}

/* 1x1 skip conv + residual h update for one slot */
__device__ __forceinline__ void skip_pos(const float* __restrict__ wk, const float* __restrict__ bk,
    const ull* __restrict__ gated, float* __restrict__ hb, int s, bool in_seq)
{
    ull acc[16];
    #pragma unroll
    for (int k = 0; k < 16; ++k) acc[k] = pack2(bk[2*k], bk[2*k+1]);
    #pragma unroll
    for (int p = 0; p < 16; ++p){
        float g0, g1; unpack2(gated[p], g0, g1);
        ull pg0 = packdup(g0), pg1 = packdup(g1);
        const ulonglong2* W0 = (const ulonglong2*)(wk + (2*p)*CH);
        const ulonglong2* W1 = (const ulonglong2*)(wk + (2*p+1)*CH);
        #pragma unroll
        for (int q = 0; q < 8; ++q){
            ulonglong2 w = W0[q];
            fma2(acc[2*q], w.x, pg0); fma2(acc[2*q+1], w.y, pg0);
            w = W1[q];
            fma2(acc[2*q], w.x, pg1); fma2(acc[2*q+1], w.y, pg1);
        }
    }
    #pragma unroll
    for (int k = 0; k < 16; ++k){
        float s0, s1; unpack2(acc[k], s0, s1);
        float* r0 = hb + (2*k)*SROW + s;
        float* r1 = hb + (2*k+1)*SROW + s;
        float n0 = in_seq ? (*r0 + fmaxf(s0, 0.f)) : 0.f;
        float n1 = in_seq ? (*r1 + fmaxf(s1, 0.f)) : 0.f;
        *r0 = n0; *r1 = n1;
    }
}

/* tail for two slots, sharing all weight loads */
__device__ __forceinline__ void tail_both(const float* __restrict__ sm,
    int sA, int sB, int tgA, int tgB, float xA, float xB, bool vA, bool vB,
    const float* __restrict__ w_dense, float& l0, float& l1)
{
    ull FA[16], FB[16];
    const float* bf = sm + OFF_BFIN;
    #pragma unroll
    for (int k = 0; k < 16; ++k){ ull t = pack2(bf[2*k], bf[2*k+1]); FA[k] = t; FB[k] = t; }
    #pragma unroll 4
    for (int ci = 0; ci < CH; ++ci){
        float wi = sm[OFF_WI + ci], bi = sm[OFF_BI + ci];
        float yA = fmaxf(sm[OFF_HB + ci*SROW + sA] - fmaxf(fmaf(xA, wi, bi), 0.f), 0.f);
        float yB = fmaxf(sm[OFF_HB + ci*SROW + sB] - fmaxf(fmaf(xB, wi, bi), 0.f), 0.f);
        ull pA = packdup(yA), pB = packdup(yB);
        const ulonglong2* Wf = (const ulonglong2*)(sm + OFF_WF + ci*CH);
        #pragma unroll
        for (int q = 0; q < 8; ++q){
            ulonglong2 w = Wf[q];
            fma2(FA[2*q], w.x, pA); fma2(FA[2*q+1], w.y, pA);
            fma2(FB[2*q], w.x, pB); fma2(FB[2*q+1], w.y, pB);
        }
    }
    if (vA){
        const float4* wd4 = (const float4*)(w_dense + (size_t)tgA * (CH*2));
        #pragma unroll
        for (int k = 0; k < 16; ++k){
            float ya, yb; unpack2(FA[k], ya, yb);
            ya = fmaxf(ya, 0.f); yb = fmaxf(yb, 0.f);
            float4 wv = __ldg(wd4 + k);
            l0 = fmaf(ya, wv.x, fmaf(yb, wv.z, l0));
            l1 = fmaf(ya, wv.y, fmaf(yb, wv.w, l1));
        }
    }
    if (vB){
        const float4* wd4 = (const float4*)(w_dense + (size_t)tgB * (CH*2));
        #pragma unroll
        for (int k = 0; k < 16; ++k){
            float ya, yb; unpack2(FB[k], ya, yb);
            ya = fmaxf(ya, 0.f); yb = fmaxf(yb, 0.f);
            float4 wv = __ldg(wd4 + k);
            l0 = fmaf(ya, wv.x, fmaf(yb, wv.z, l0));
            l1 = fmaf(ya, wv.y, fmaf(yb, wv.w, l1));
        }
    }
}

__global__ void __launch_bounds__(NT, 1)
wavenet_kernel(const float* __restrict__ x,
               const float* __restrict__ w_init,  const float* __restrict__ b_init,
               const float* __restrict__ w_tanh,  const float* __restrict__ b_tanh,
               const float* __restrict__ w_sig,   const float* __restrict__ b_sig,
               const float* __restrict__ w_skip,  const float* __restrict__ b_skip,
               const float* __restrict__ w_final, const float* __restrict__ b_final,
               const float* __restrict__ w_dense, const float* __restrict__ b_dense,
               float* __restrict__ out)
{
    extern __shared__ float sm[];
    float* hb = sm + OFF_HB;
    const int tid  = threadIdx.x;
    const int b    = blockIdx.x / NTILES;
    const int tile = blockIdx.x - b*NTILES;
    const int t0   = tile * T_TILE;

    const int sl0 = tid, sl1 = tid + NT, sl2 = tid + 2*NT, sl3 = tid + 3*NT;
    const int tg0 = t0 - HALO + sl0, tg1 = t0 - HALO + sl1;
    const int tg2 = t0 - HALO + sl2, tg3 = t0 - HALO + sl3;
    const bool in0 = (tg0 >= 0) && (tg0 < TLEN);
    const bool in1 = (tg1 < TLEN);
    const bool in2 = (tg2 < TLEN);
    const bool in3 = (tg3 < TLEN);
    const float* xb = x + (size_t)b*TLEN;
    const float x0 = in0 ? xb[tg0] : 0.f;
    const float x1 = in1 ? xb[tg1] : 0.f;
    const float x2 = in2 ? xb[tg2] : 0.f;
    const float x3 = in3 ? xb[tg3] : 0.f;

    /* preload block-0 weights, final weights, final bias, init weights */
    copyw(sm + OFF_BUF0, w_tanh, w_sig, w_skip, b_tanh, b_sig, b_skip, 0, tid);
    {
        const float4* gf = (const float4*)w_final;
        float4* f4 = (float4*)(sm + OFF_WF);
        for (int j = tid; j < 256; j += NT) f4[j] = gf[j];
        if (tid < 32){
            sm[OFF_BFIN + tid] = b_final[tid];
            sm[OFF_WI   + tid] = w_init[tid];
            sm[OFF_BI   + tid] = b_init[tid];
        }
    }
    /* initial h = relu(x*w_init + b_init), transposed [c][slot], zero outside sequence */
    #pragma unroll 4
    for (int c = 0; c < CH; ++c){
        float wi = __ldg(w_init + c), bi = __ldg(b_init + c);
        float* row = hb + c*SROW;
        row[sl0] = in0 ? fmaxf(fmaf(x0, wi, bi), 0.f) : 0.f;
        row[sl1] = in1 ? fmaxf(fmaf(x1, wi, bi), 0.f) : 0.f;
        row[sl2] = in2 ? fmaxf(fmaf(x2, wi, bi), 0.f) : 0.f;
        row[sl3] = in3 ? fmaxf(fmaf(x3, wi, bi), 0.f) : 0.f;
    }

    ull gt0[16], gt1[16], gt2[16], gt3[16];

    #pragma unroll 1
    for (int blk = 0; blk < NB; ++blk){
        __syncthreads();   /* SA: weights for blk + h writes visible */
        const float* buf = sm + OFF_BUF0 + (blk & 1)*BUFSZ;
        if (blk + 1 < NB)  /* prefetch next block's weights into the other buffer */
            copyw(sm + OFF_BUF0 + ((blk+1) & 1)*BUFSZ,
                  w_tanh, w_sig, w_skip, b_tanh, b_sig, b_skip, blk+1, tid);

        const int d = 1 << blk;

        #pragma unroll
        for (int e = 0; e < 4; ++e){   /* fully unrolled -> static gt indexing */
            conv8x4(buf + B_WT + e*8, buf + B_WS + e*8,
                    buf + B_BT + e*8, buf + B_BS + e*8,
                    hb, tid, d,
                    gt0 + 4*e, gt1 + 4*e, gt2 + 4*e, gt3 + 4*e);
        }
        __syncthreads();   /* SB: all h reads done */
        skip_pos(buf + B_WK, buf + B_BK, gt0, hb, sl0, in0);
        skip_pos(buf + B_WK, buf + B_BK, gt1, hb, sl1, in1);
        skip_pos(buf + B_WK, buf + B_BK, gt2, hb, sl2, in2);
        skip_pos(buf + B_WK, buf + B_BK, gt3, hb, sl3, in3);
    }

    /* tail: only own slots read -> no extra sync needed */
    float l0 = 0.f, l1 = 0.f;
    const bool v0 = (sl0 >= HALO) && (sl0 < HALO + T_TILE) && in0;
    const bool v1 = (sl1 >= HALO) && (sl1 < HALO + T_TILE) && in1;
    const bool v2 = (sl2 >= HALO) && (sl2 < HALO + T_TILE) && in2;
    const bool v3 = (sl3 >= HALO) && (sl3 < HALO + T_TILE) && in3;
    if (v0 || v1) tail_both(sm, sl0, sl1, tg0, tg1, x0, x1, v0, v1, w_dense, l0, l1);
    if (v2 || v3) tail_both(sm, sl2, sl3, tg2, tg3, x2, x3, v2, v3, w_dense, l0, l1);

    #pragma unroll
    for (int off = 16; off > 0; off >>= 1){
        l0 += __shfl_down_sync(0xffffffffu, l0, off);
        l1 += __shfl_down_sync(0xffffffffu, l1, off);
    }
    const int wid = tid >> 5, lane = tid & 31;
    float* sred = sm + OFF_RED;
    if (lane == 0){ sred[wid*2] = l0; sred[wid*2+1] = l1; }
    __syncthreads();
    if (tid == 0){
        float s0 = 0.f, s1 = 0.f;
        #pragma unroll
        for (int w = 0; w < NWARPS; ++w){ s0 += sred[w*2]; s1 += sred[w*2+1]; }
        g_partials[blockIdx.x*2 + 0] = s0;
        g_partials[blockIdx.x*2 + 1] = s1;
        __threadfence();
        unsigned int prev = atomicAdd(&g_count, 1u);
        sm[OFF_DONE] = (prev == NCTAS - 1) ? 1.f : 0.f;
    }
    __syncthreads();

    /* last CTA finalizes: deterministic fixed-order sums + softmax */
    if (sm[OFF_DONE] != 0.f){
        __threadfence();
        if (tid < BATCH){
            float s0 = b_dense[0], s1 = b_dense[1];
            for (int t = 0; t < NTILES; ++t){
                s0 += g_partials[(tid*NTILES + t)*2 + 0];
                s1 += g_partials[(tid*NTILES + t)*2 + 1];
            }
            float m = fmaxf(s0, s1);
            float e0 = expf(s0 - m), e1 = expf(s1 - m);
            float inv = 1.f / (e0 + e1);
            out[tid*2 + 0] = e0*inv;
            out[tid*2 + 1] = e1*inv;
        }
        if (tid == 0) g_count = 0;   /* reset for next (graph-replayed) launch */
    }
}

extern "C" void kernel_launch(void* const* d_in, const int* in_sizes, int n_in,
                              void* d_out, int out_size)
{
    const float* x       = (const float*)d_in[0];
    const float* w_init  = (const float*)d_in[1];
    const float* b_init  = (const float*)d_in[2];
    const float* w_tanh  = (const float*)d_in[3];
    const float* b_tanh  = (const float*)d_in[4];
    const float* w_sig   = (const float*)d_in[5];
    const float* b_sig   = (const float*)d_in[6];
    const float* w_skip  = (const float*)d_in[7];
    const float* b_skip  = (const float*)d_in[8];
    const float* w_final = (const float*)d_in[9];
    const float* b_final = (const float*)d_in[10];
    const float* w_dense = (const float*)d_in[11];
    const float* b_dense = (const float*)d_in[12];

    cudaFuncSetAttribute(wavenet_kernel,
                         cudaFuncAttributeMaxDynamicSharedMemorySize, SMEM_BYTES);

    wavenet_kernel<<<NCTAS, NT, SMEM_BYTES>>>(
        x, w_init, b_init, w_tanh, b_tanh, w_sig, b_sig,
        w_skip, b_skip, w_final, b_final, w_dense, b_dense, (float*)d_out);
}

// round 9
// speedup vs baseline: 2.4596x; 2.4596x over previous
#include <cuda_runtime.h>

typedef unsigned long long ull;

#define BATCH   8
#define TLEN    16384
#define CH      32
#define NB      6
#define NT      544
#define NWARPS  17
#define HALO    63
#define SLOTS   1088            /* 2 slots per thread */
#define SROW    1088
#define T_TILE  962             /* SLOTS - 2*HALO */
#define NTILES  18              /* 18*962 = 17316 >= 16384 */
#define NCTAS   (BATCH*NTILES)  /* 144 */

#define BUFSZ     7264          /* gate 6144 + skip 1024 + 3x32 biases */
#define OFF_HB    0
#define OFF_BUF0  (CH*SROW)
#define OFF_BUF1  (OFF_BUF0 + BUFSZ)
#define OFF_WF    (OFF_BUF1 + BUFSZ)
#define OFF_BFIN  (OFF_WF + 1024)
#define OFF_WI    (OFF_BFIN + 32)
#define OFF_BI    (OFF_WI + 32)
#define OFF_RED   (OFF_BI + 32)
#define OFF_DONE  (OFF_RED + 2*NWARPS)
#define SMEM_FLOATS (OFF_DONE + 1)
#define SMEM_BYTES  (SMEM_FLOATS*4)     /* ~202 KB */

/* in-buffer float offsets */
#define B_WT 0
#define B_WS 3072
#define B_WK 6144
#define B_BT 7168
#define B_BS 7200
#define B_BK 7232

__device__ float g_partials[NCTAS*2];
__device__ unsigned int g_count;

__device__ __forceinline__ void fma2(ull& d, ull a, ull b){
    asm("fma.rn.f32x2 %0, %1, %2, %0;" : "+l"(d) : "l"(a), "l"(b));
}
__device__ __forceinline__ ull pack2(float lo, float hi){
    ull r; asm("mov.b64 %0, {%1, %2};" : "=l"(r) : "f"(lo), "f"(hi)); return r;
}
__device__ __forceinline__ ull packdup(float v){ return pack2(v, v); }
__device__ __forceinline__ void unpack2(ull v, float& lo, float& hi){
    asm("mov.b64 {%0, %1}, %2;" : "=f"(lo), "=f"(hi) : "l"(v));
}
__device__ __forceinline__ float ex2_(float x){
    float y; asm("ex2.approx.f32 %0, %1;" : "=f"(y) : "f"(x)); return y;
}
__device__ __forceinline__ float rcp_(float x){
    float y; asm("rcp.approx.f32 %0, %1;" : "=f"(y) : "f"(x)); return y;
}
/* tanh(a)*sigmoid(g) = (e1-1)*e2 / ((e1+1)(e2+1)), e1=e^{2a}, e2=e^{g}; clamps keep exp finite */
__device__ __forceinline__ float gateval(float a, float g){
    a = fminf(fmaxf(a, -15.f), 15.f);
    g = fminf(fmaxf(g, -30.f), 30.f);
    float e1 = ex2_(a * 2.8853900817779268f);
    float e2 = ex2_(g * 1.4426950408889634f);
    return (e1 - 1.f) * e2 * rcp_((e1 + 1.f) * (e2 + 1.f));
}

__device__ __forceinline__ void copyw(float* dst,
    const float* wt, const float* ws, const float* wk,
    const float* bt, const float* bs, const float* bk, int blk, int tid)
{
    const float4* g1 = (const float4*)(wt + blk*3072);
    const float4* g2 = (const float4*)(ws + blk*3072);
    const float4* g3 = (const float4*)(wk + blk*1024);
    float4* d = (float4*)dst;
    for (int j = tid; j < 768; j += NT) d[j]        = g1[j];
    for (int j = tid; j < 768; j += NT) d[768 + j]  = g2[j];
    for (int j = tid; j < 256; j += NT) d[1536 + j] = g3[j];
    if (tid < 32){
        dst[B_BT + tid] = bt[blk*32 + tid];
        dst[B_BS + tid] = bs[blk*32 + tid];
        dst[B_BK + tid] = bk[blk*32 + tid];
    }
}

/* one tap, one branch: 4 channel-pairs (8 ch) x 2 positions = 8 fma2, 2 LDS.128 */
#define TAP8(ACCA, ACCB, WA, WB, HA, HB) \
    fma2(ACCA[0],WA.x,HA); fma2(ACCA[1],WA.y,HA); fma2(ACCA[2],WB.x,HA); fma2(ACCA[3],WB.y,HA); \
    fma2(ACCB[0],WA.x,HB); fma2(ACCB[1],WA.y,HB); fma2(ACCB[2],WB.x,HB); fma2(ACCB[3],WB.y,HB)

/* gate conv: 8 output channels (group), 2 positions; one h load feeds 8 channels */
__device__ __forceinline__ void conv8x2(
    const float* __restrict__ wt, const float* __restrict__ ws,
    const float* __restrict__ bt, const float* __restrict__ bs,
    const float* __restrict__ hb,
    int pmA, int s0A, int ppA, int pmB, int s0B, int ppB,
    ull* __restrict__ gA, ull* __restrict__ gB)
{
    ull tA[4], uA[4], tB[4], uB[4];
    #pragma unroll
    for (int j = 0; j < 4; ++j){
        ull bT = pack2(bt[2*j], bt[2*j+1]);
        ull bS = pack2(bs[2*j], bs[2*j+1]);
        tA[j] = bT; tB[j] = bT; uA[j] = bS; uB[j] = bS;
    }
    #pragma unroll 2
    for (int ci = 0; ci < CH; ++ci){
        const float* hr  = hb + ci*SROW;
        const float* wtc = wt + ci*CH;
        const float* wsc = ws + ci*CH;
        /* tap 0 : t - d */
        {
            ull hA = packdup(hr[pmA]), hB = packdup(hr[pmB]);
            ulonglong2 wa = *(const ulonglong2*)(wtc);
            ulonglong2 wb = *(const ulonglong2*)(wtc + 4);
            ulonglong2 va = *(const ulonglong2*)(wsc);
            ulonglong2 vb = *(const ulonglong2*)(wsc + 4);
            TAP8(tA, tB, wa, wb, hA, hB);
            TAP8(uA, uB, va, vb, hA, hB);
        }
        /* tap 1 : t */
        {
            ull hA = packdup(hr[s0A]), hB = packdup(hr[s0B]);
            ulonglong2 wa = *(const ulonglong2*)(wtc + 1024);
            ulonglong2 wb = *(const ulonglong2*)(wtc + 1028);
            ulonglong2 va = *(const ulonglong2*)(wsc + 1024);
            ulonglong2 vb = *(const ulonglong2*)(wsc + 1028);
            TAP8(tA, tB, wa, wb, hA, hB);
            TAP8(uA, uB, va, vb, hA, hB);
        }
        /* tap 2 : t + d */
        {
            ull hA = packdup(hr[ppA]), hB = packdup(hr[ppB]);
            ulonglong2 wa = *(const ulonglong2*)(wtc + 2048);
            ulonglong2 wb = *(const ulonglong2*)(wtc + 2052);
            ulonglong2 va = *(const ulonglong2*)(wsc + 2048);
            ulonglong2 vb = *(const ulonglong2*)(wsc + 2052);
            TAP8(tA, tB, wa, wb, hA, hB);
            TAP8(uA, uB, va, vb, hA, hB);
        }
    }
    #pragma unroll
    for (int j = 0; j < 4; ++j){
        float a0,a1,b0,b1;
        unpack2(tA[j],a0,a1); unpack2(uA[j],b0,b1);
        gA[j] = pack2(gateval(a0,b0), gateval(a1,b1));
        unpack2(tB[j],a0,a1); unpack2(uB[j],b0,b1);
        gB[j] = pack2(gateval(a0,b0), gateval(a1,b1));
    }
}

/* 1x1 skip conv + residual h update for one slot */
__device__ __forceinline__ void skip_pos(const float* __restrict__ wk, const float* __restrict__ bk,
    const ull* __restrict__ gated, float* __restrict__ hb, int s, bool in_seq)
{
    ull acc[16];
    #pragma unroll
    for (int k = 0; k < 16; ++k) acc[k] = pack2(bk[2*k], bk[2*k+1]);
    #pragma unroll
    for (int p = 0; p < 16; ++p){
        float g0, g1; unpack2(gated[p], g0, g1);
        ull pg0 = packdup(g0), pg1 = packdup(g1);
        const ulonglong2* W0 = (const ulonglong2*)(wk + (2*p)*CH);
        const ulonglong2* W1 = (const ulonglong2*)(wk + (2*p+1)*CH);
        #pragma unroll
        for (int q = 0; q < 8; ++q){
            ulonglong2 w = W0[q];
            fma2(acc[2*q], w.x, pg0); fma2(acc[2*q+1], w.y, pg0);
            w = W1[q];
            fma2(acc[2*q], w.x, pg1); fma2(acc[2*q+1], w.y, pg1);
        }
    }
    #pragma unroll
    for (int k = 0; k < 16; ++k){
        float s0, s1; unpack2(acc[k], s0, s1);
        float* r0 = hb + (2*k)*SROW + s;
        float* r1 = hb + (2*k+1)*SROW + s;
        float n0 = in_seq ? (*r0 + fmaxf(s0, 0.f)) : 0.f;
        float n1 = in_seq ? (*r1 + fmaxf(s1, 0.f)) : 0.f;
        *r0 = n0; *r1 = n1;
    }
}

/* tail for both slots, sharing all weight loads */
__device__ __forceinline__ void tail_both(const float* __restrict__ sm,
    int sA, int sB, int tgA, int tgB, float xA, float xB, bool vA, bool vB,
    const float* __restrict__ w_dense, float& l0, float& l1)
{
    ull FA[16], FB[16];
    const float* bf = sm + OFF_BFIN;
    #pragma unroll
    for (int k = 0; k < 16; ++k){ ull t = pack2(bf[2*k], bf[2*k+1]); FA[k] = t; FB[k] = t; }
    #pragma unroll 4
    for (int ci = 0; ci < CH; ++ci){
        float wi = sm[OFF_WI + ci], bi = sm[OFF_BI + ci];
        float yA = fmaxf(sm[OFF_HB + ci*SROW + sA] - fmaxf(fmaf(xA, wi, bi), 0.f), 0.f);
        float yB = fmaxf(sm[OFF_HB + ci*SROW + sB] - fmaxf(fmaf(xB, wi, bi), 0.f), 0.f);
        ull pA = packdup(yA), pB = packdup(yB);
        const ulonglong2* Wf = (const ulonglong2*)(sm + OFF_WF + ci*CH);
        #pragma unroll
        for (int q = 0; q < 8; ++q){
            ulonglong2 w = Wf[q];
            fma2(FA[2*q], w.x, pA); fma2(FA[2*q+1], w.y, pA);
            fma2(FB[2*q], w.x, pB); fma2(FB[2*q+1], w.y, pB);
        }
    }
    if (vA){
        const float4* wd4 = (const float4*)(w_dense + (size_t)tgA * (CH*2));
        #pragma unroll
        for (int k = 0; k < 16; ++k){
            float ya, yb; unpack2(FA[k], ya, yb);
            ya = fmaxf(ya, 0.f); yb = fmaxf(yb, 0.f);
            float4 wv = __ldg(wd4 + k);
            l0 = fmaf(ya, wv.x, fmaf(yb, wv.z, l0));
            l1 = fmaf(ya, wv.y, fmaf(yb, wv.w, l1));
        }
    }
    if (vB){
        const float4* wd4 = (const float4*)(w_dense + (size_t)tgB * (CH*2));
        #pragma unroll
        for (int k = 0; k < 16; ++k){
            float ya, yb; unpack2(FB[k], ya, yb);
            ya = fmaxf(ya, 0.f); yb = fmaxf(yb, 0.f);
            float4 wv = __ldg(wd4 + k);
            l0 = fmaf(ya, wv.x, fmaf(yb, wv.z, l0));
            l1 = fmaf(ya, wv.y, fmaf(yb, wv.w, l1));
        }
    }
}

__global__ void __launch_bounds__(NT, 1)
wavenet_kernel(const float* __restrict__ x,
               const float* __restrict__ w_init,  const float* __restrict__ b_init,
               const float* __restrict__ w_tanh,  const float* __restrict__ b_tanh,
               const float* __restrict__ w_sig,   const float* __restrict__ b_sig,
               const float* __restrict__ w_skip,  const float* __restrict__ b_skip,
               const float* __restrict__ w_final, const float* __restrict__ b_final,
               const float* __restrict__ w_dense, const float* __restrict__ b_dense,
               float* __restrict__ out)
{
    extern __shared__ float sm[];
    float* hb = sm + OFF_HB;
    const int tid  = threadIdx.x;
    const int b    = blockIdx.x / NTILES;
    const int tile = blockIdx.x - b*NTILES;
    const int t0   = tile * T_TILE;

    const int sA = tid, sB = tid + NT;
    const int tgA = t0 - HALO + sA;
    const int tgB = t0 - HALO + sB;
    const bool inA = (tgA >= 0) && (tgA < TLEN);
    const bool inB = (tgB >= 0) && (tgB < TLEN);
    const float xA = inA ? x[(size_t)b*TLEN + tgA] : 0.f;
    const float xB = inB ? x[(size_t)b*TLEN + tgB] : 0.f;

    /* preload block-0 weights, final weights, final bias, init weights */
    copyw(sm + OFF_BUF0, w_tanh, w_sig, w_skip, b_tanh, b_sig, b_skip, 0, tid);
    {
        const float4* gf = (const float4*)w_final;
        float4* f4 = (float4*)(sm + OFF_WF);
        for (int j = tid; j < 256; j += NT) f4[j] = gf[j];
        if (tid < 32){
            sm[OFF_BFIN + tid] = b_final[tid];
            sm[OFF_WI   + tid] = w_init[tid];
            sm[OFF_BI   + tid] = b_init[tid];
        }
    }
    /* initial h = relu(x*w_init + b_init), transposed [c][slot], zero outside sequence */
    #pragma unroll 4
    for (int c = 0; c < CH; ++c){
        float wi = __ldg(w_init + c), bi = __ldg(b_init + c);
        hb[c*SROW + sA] = inA ? fmaxf(fmaf(xA, wi, bi), 0.f) : 0.f;
        hb[c*SROW + sB] = inB ? fmaxf(fmaf(xB, wi, bi), 0.f) : 0.f;
    }

    ull gA[16], gB[16];

    #pragma unroll 1
    for (int blk = 0; blk < NB; ++blk){
        __syncthreads();   /* SA: weights for blk + h writes visible */
        const float* buf = sm + OFF_BUF0 + (blk & 1)*BUFSZ;
        if (blk + 1 < NB)  /* prefetch next block's weights into the other buffer */
            copyw(sm + OFF_BUF0 + ((blk+1) & 1)*BUFSZ,
                  w_tanh, w_sig, w_skip, b_tanh, b_sig, b_skip, blk+1, tid);

        const int d = 1 << blk;
        int pmA = sA - d; if (pmA < 0) pmA = 0;
        int ppA = sA + d; if (ppA > SLOTS-1) ppA = SLOTS-1;
        int pmB = sB - d; if (pmB < 0) pmB = 0;
        int ppB = sB + d; if (ppB > SLOTS-1) ppB = SLOTS-1;

        #pragma unroll
        for (int e = 0; e < 4; ++e){   /* FULLY unrolled -> static gA/gB indexing */
            conv8x2(buf + B_WT + e*8, buf + B_WS + e*8,
                    buf + B_BT + e*8, buf + B_BS + e*8,
                    hb, pmA, sA, ppA, pmB, sB, ppB,
                    gA + 4*e, gB + 4*e);
        }
        __syncthreads();   /* SB: all h reads done */
        skip_pos(buf + B_WK, buf + B_BK, gA, hb, sA, inA);
        skip_pos(buf + B_WK, buf + B_BK, gB, hb, sB, inB);
    }

    /* tail: only own slots read -> no extra sync needed */
    float l0 = 0.f, l1 = 0.f;
    const bool vA = (sA >= HALO) && (sA < HALO + T_TILE) && (tgA < TLEN);
    const bool vB = (sB >= HALO) && (sB < HALO + T_TILE) && (tgB < TLEN);
    if (vA || vB)
        tail_both(sm, sA, sB, tgA, tgB, xA, xB, vA, vB, w_dense, l0, l1);

    #pragma unroll
    for (int off = 16; off > 0; off >>= 1){
        l0 += __shfl_down_sync(0xffffffffu, l0, off);
        l1 += __shfl_down_sync(0xffffffffu, l1, off);
    }
    const int wid = tid >> 5, lane = tid & 31;
    float* sred = sm + OFF_RED;
    if (lane == 0){ sred[wid*2] = l0; sred[wid*2+1] = l1; }
    __syncthreads();
    if (tid == 0){
        float s0 = 0.f, s1 = 0.f;
        #pragma unroll
        for (int w = 0; w < NWARPS; ++w){ s0 += sred[w*2]; s1 += sred[w*2+1]; }
        g_partials[blockIdx.x*2 + 0] = s0;
        g_partials[blockIdx.x*2 + 1] = s1;
        __threadfence();
        unsigned int prev = atomicAdd(&g_count, 1u);
        sm[OFF_DONE] = (prev == NCTAS - 1) ? 1.f : 0.f;
    }
    __syncthreads();

    /* last CTA finalizes: deterministic fixed-order sums + softmax */
    if (sm[OFF_DONE] != 0.f){
        __threadfence();
        if (tid < BATCH){
            float s0 = b_dense[0], s1 = b_dense[1];
            for (int t = 0; t < NTILES; ++t){
                s0 += g_partials[(tid*NTILES + t)*2 + 0];
                s1 += g_partials[(tid*NTILES + t)*2 + 1];
            }
            float m = fmaxf(s0, s1);
            float e0 = expf(s0 - m), e1 = expf(s1 - m);
            float inv = 1.f / (e0 + e1);
            out[tid*2 + 0] = e0*inv;
            out[tid*2 + 1] = e1*inv;
        }
        if (tid == 0) g_count = 0;   /* reset for next (graph-replayed) launch */
    }
}

extern "C" void kernel_launch(void* const* d_in, const int* in_sizes, int n_in,
                              void* d_out, int out_size)
{
    const float* x       = (const float*)d_in[0];
    const float* w_init  = (const float*)d_in[1];
    const float* b_init  = (const float*)d_in[2];
    const float* w_tanh  = (const float*)d_in[3];
    const float* b_tanh  = (const float*)d_in[4];
    const float* w_sig   = (const float*)d_in[5];
    const float* b_sig   = (const float*)d_in[6];
    const float* w_skip  = (const float*)d_in[7];
    const float* b_skip  = (const float*)d_in[8];
    const float* w_final = (const float*)d_in[9];
    const float* b_final = (const float*)d_in[10];
    const float* w_dense = (const float*)d_in[11];
    const float* b_dense = (const float*)d_in[12];

    cudaFuncSetAttribute(wavenet_kernel,
                         cudaFuncAttributeMaxDynamicSharedMemorySize, SMEM_BYTES);

    wavenet_kernel<<<NCTAS, NT, SMEM_BYTES>>>(
        x, w_init, b_init, w_tanh, b_tanh, w_sig, b_sig,
        w_skip, b_skip, w_final, b_final, w_dense, b_dense, (float*)d_out);
}